// round 12
// baseline (speedup 1.0000x reference)
#include <cuda_runtime.h>
#include <cuda_fp16.h>

// ---------------------------------------------------------------------------
// GCN (CSR gather-reduce, fp16 intermediates, HMMA GEMM):
//   t1 = (ns . x) @ W1                                   (fp16 out)
//   agg1 = A t1                                          (fp16, raw)
//   t2 = (relu(agg1 . nd + b1) . ns) @ W2                (transform in GEMM2)
//   h2 = relu((A t2) . nd + b2)                          (fp32 -> d_out)
//   hg = sum-pool(h2) (parallel partials); readout divides by count
// ---------------------------------------------------------------------------

#define D 128
#define MAX_NODES 100096
#define MAX_EDGES 1700000
#define MAX_FEAT  12812288   // MAX_NODES * 128

#define WS_STRIDE 136
#define XS_STRIDE 136
#define POOL_SLICES 16

// One contiguous zeroed region: hist (2*MAX_NODES int) + hg (64*128 float)
#define ZERO_BYTES (2 * MAX_NODES * 4 + 64 * D * 4)
__device__ __align__(16) unsigned char g_zeroed[ZERO_BYTES];

__device__ int    g_rowptr[MAX_NODES + 1];
__device__ int    g_cursor[MAX_NODES];
__device__ int    g_esrc[MAX_EDGES];
__device__ int    g_bsums[256];
__device__ float  g_norm[2 * MAX_NODES];       // norm_src, norm_dst
__device__ __half g_wh[2 * D * D];             // fp16 W1, W2
__device__ __half g_t[MAX_FEAT];               // GEMM output (fp16)
__device__ __half g_agg1[MAX_FEAT];            // layer-1 raw aggregate (fp16)

// ---------------------------------------------------------------------------
// fused: blocks 0..31 convert W1/W2 -> fp16; blocks 32.. do edge histograms
// ---------------------------------------------------------------------------
__global__ void convert_hist(const float* __restrict__ W1,
                             const float* __restrict__ W2,
                             __half* __restrict__ wh,
                             const int* __restrict__ src,
                             const int* __restrict__ dst,
                             int* __restrict__ hdst, int* __restrict__ hsrc,
                             int nE) {
    int b = blockIdx.x;
    int t = threadIdx.x;
    if (b < 32) {
        int i = b * 256 + t;                 // float2 units, 8192 total
        const float2* w1 = (const float2*)W1;
        const float2* w2 = (const float2*)W2;
        float2 a = w1[i];
        float2 c = w2[i];
        ((__half2*)wh)[i] = __floats2half2_rn(a.x, a.y);
        ((__half2*)wh)[i + D * D / 2] = __floats2half2_rn(c.x, c.y);
    } else {
        int e = ((b - 32) * 256 + t) * 2;
        if (e + 1 < nE) {
            int2 s = *(const int2*)(src + e);
            int2 d = *(const int2*)(dst + e);
            atomicAdd(&hsrc[s.x], 1); atomicAdd(&hsrc[s.y], 1);
            atomicAdd(&hdst[d.x], 1); atomicAdd(&hdst[d.y], 1);
        } else if (e < nE) {
            atomicAdd(&hsrc[src[e]], 1);
            atomicAdd(&hdst[dst[e]], 1);
        }
    }
}

// ---------------------------------------------------------------------------
// fused: block sums for scan + norm computation (single pass over hists)
// ---------------------------------------------------------------------------
__global__ void scan_bsums_norm(const int* __restrict__ hdst,
                                const int* __restrict__ hsrc,
                                int* __restrict__ bsums,
                                float* __restrict__ ns, float* __restrict__ nd,
                                int n) {
    __shared__ int sh[256];
    int b = blockIdx.x, t = threadIdx.x;
    int base = b * 1024 + t * 4;
    int s = 0;
#pragma unroll
    for (int k = 0; k < 4; k++) {
        int i = base + k;
        if (i < n) {
            int hd = hdst[i];
            s += hd;
            nd[i] = rsqrtf(fmaxf((float)hd, 1.0f));
            ns[i] = rsqrtf(fmaxf((float)hsrc[i], 1.0f));
        }
    }
    sh[t] = s; __syncthreads();
    for (int off = 128; off > 0; off >>= 1) {
        if (t < off) sh[t] += sh[t + off];
        __syncthreads();
    }
    if (t == 0) bsums[b] = sh[0];
}

// expand with inline block-offset scan
__global__ void scan_expand(const int* __restrict__ hist,
                            const int* __restrict__ bsums,
                            int* __restrict__ rowptr, int* __restrict__ cursor,
                            int n, int nE, int nb) {
    __shared__ int sbs[256];
    __shared__ int sh[256];
    int b = blockIdx.x, t = threadIdx.x;

    int v0 = (t < nb) ? bsums[t] : 0;
    sbs[t] = v0; __syncthreads();
    for (int off = 1; off < 256; off <<= 1) {
        int u = (t >= off) ? sbs[t - off] : 0;
        __syncthreads();
        sbs[t] += u;
        __syncthreads();
    }
    int boff = (b == 0) ? 0 : sbs[b - 1];

    int base = b * 1024 + t * 4;
    int v[4]; int s = 0;
#pragma unroll
    for (int k = 0; k < 4; k++) {
        int i = base + k;
        v[k] = (i < n) ? hist[i] : 0;
        s += v[k];
    }
    sh[t] = s; __syncthreads();
    for (int off = 1; off < 256; off <<= 1) {
        int u = (t >= off) ? sh[t - off] : 0;
        __syncthreads();
        sh[t] += u;
        __syncthreads();
    }
    int off = boff + sh[t] - s;
#pragma unroll
    for (int k = 0; k < 4; k++) {
        int i = base + k;
        if (i < n) { rowptr[i] = off; cursor[i] = off; }
        off += v[k];
    }
    if (b == 0 && t == 0) rowptr[n] = nE;
}

__global__ void scatter_edges(const int* __restrict__ src,
                              const int* __restrict__ dst,
                              int* __restrict__ cursor,
                              int* __restrict__ esrc, int nE) {
    int e2 = blockIdx.x * blockDim.x + threadIdx.x;
    int e = e2 * 2;
    if (e + 1 < nE) {
        int2 s = *(const int2*)(src + e);
        int2 d = *(const int2*)(dst + e);
        int p0 = atomicAdd(&cursor[d.x], 1);
        esrc[p0] = s.x;
        int p1 = atomicAdd(&cursor[d.y], 1);
        esrc[p1] = s.y;
    } else if (e < nE) {
        int p = atomicAdd(&cursor[dst[e]], 1);
        esrc[p] = src[e];
    }
}

// ---------------------------------------------------------------------------
// HMMA helpers
// ---------------------------------------------------------------------------
__device__ __forceinline__ void ldsm_x4(unsigned& r0, unsigned& r1,
                                        unsigned& r2, unsigned& r3,
                                        unsigned addr) {
    asm volatile("ldmatrix.sync.aligned.m8n8.x4.shared.b16 {%0,%1,%2,%3}, [%4];"
                 : "=r"(r0), "=r"(r1), "=r"(r2), "=r"(r3) : "r"(addr));
}
__device__ __forceinline__ void ldsm_x4_t(unsigned& r0, unsigned& r1,
                                          unsigned& r2, unsigned& r3,
                                          unsigned addr) {
    asm volatile("ldmatrix.sync.aligned.m8n8.x4.trans.shared.b16 {%0,%1,%2,%3}, [%4];"
                 : "=r"(r0), "=r"(r1), "=r"(r2), "=r"(r3) : "r"(addr));
}
__device__ __forceinline__ void mma16816(float* d, const unsigned* a,
                                         unsigned b0, unsigned b1) {
    asm volatile(
        "mma.sync.aligned.m16n8k16.row.col.f32.f16.f16.f32 "
        "{%0,%1,%2,%3}, {%4,%5,%6,%7}, {%8,%9}, {%0,%1,%2,%3};"
        : "+f"(d[0]), "+f"(d[1]), "+f"(d[2]), "+f"(d[3])
        : "r"(a[0]), "r"(a[1]), "r"(a[2]), "r"(a[3]), "r"(b0), "r"(b1));
}

// ---------------------------------------------------------------------------
// Fused HMMA GEMM: Y[r] = f(X[r]) @ W, K = N = 128, fp16 in / fp32 acc.
// W pre-converted fp16. 64-row tile, 8 warps (4 row x 2 col), acc[8][4].
// MODE 0 (TIN=float): f(x)[k] = x[k] * nsrc[r]
// MODE 1 (TIN=half):  f(x)[k] = relu(x[k]*ndst[r] + bias[k]) * nsrc[r]
// ---------------------------------------------------------------------------
template<typename TIN, int MODE>
__global__ __launch_bounds__(256, 1) void gemm_mma(
    const TIN* __restrict__ X, const __half* __restrict__ Wh,
    const float* __restrict__ bias, const float* __restrict__ nsrc,
    const float* __restrict__ ndst, __half* __restrict__ Y, int nRows)
{
    extern __shared__ __half sm[];
    __half* Ws = sm;                        // 128 x WS_STRIDE
    __half* Xs = sm + D * WS_STRIDE;        // 64 x XS_STRIDE
    const int tid = threadIdx.x;
    const int row0 = blockIdx.x * 64;

    // W (fp16 global) -> smem: pure uint4 copy (2048 uint4)
    {
        const uint4* Wg = (const uint4*)Wh;
#pragma unroll
        for (int i = 0; i < 8; i++) {
            int idx = tid + i * 256;        // uint4 idx over 2048
            int r = idx >> 4;               // 16 uint4 (128 halfs) per row
            int c = (idx & 15) * 8;
            *(uint4*)&Ws[r * WS_STRIDE + c] = Wg[idx];
        }
    }
    // X tile: 64 rows x 32 chunks(4), transform in fp32, pack fp16
    {
#pragma unroll
        for (int i = 0; i < 8; i++) {
            int linear = tid + i * 256;     // 2048 = 64 rows * 32 chunks
            int row = linear >> 5;
            int c4  = linear & 31;
            int gr  = row0 + row;
            float4 v = make_float4(0.f, 0.f, 0.f, 0.f);
            if (gr < nRows) {
                if constexpr (sizeof(TIN) == 4) {
                    v = ((const float4*)(X + (size_t)gr * D))[c4];
                } else {
                    uint2 u = ((const uint2*)(X + (size_t)gr * D))[c4];
                    float2 f0 = __half22float2(*(const __half2*)&u.x);
                    float2 f1 = __half22float2(*(const __half2*)&u.y);
                    v = make_float4(f0.x, f0.y, f1.x, f1.y);
                }
                if (MODE == 0) {
                    float s = nsrc[gr];
                    v.x *= s; v.y *= s; v.z *= s; v.w *= s;
                } else {
                    float a = ndst[gr];
                    float s = nsrc[gr];
                    float4 bb = ((const float4*)bias)[c4];
                    v.x = fmaxf(fmaf(v.x, a, bb.x), 0.f) * s;
                    v.y = fmaxf(fmaf(v.y, a, bb.y), 0.f) * s;
                    v.z = fmaxf(fmaf(v.z, a, bb.z), 0.f) * s;
                    v.w = fmaxf(fmaf(v.w, a, bb.w), 0.f) * s;
                }
            }
            __half2 h0 = __floats2half2_rn(v.x, v.y);
            __half2 h1 = __floats2half2_rn(v.z, v.w);
            uint2 p;
            p.x = *(unsigned*)&h0; p.y = *(unsigned*)&h1;
            *(uint2*)&Xs[row * XS_STRIDE + c4 * 4] = p;
        }
    }
    __syncthreads();

    const int warp = tid >> 5;
    const int lane = tid & 31;
    const int m0 = (warp & 3) * 16;
    const int n0 = (warp >> 2) * 64;

    float acc[8][4];
#pragma unroll
    for (int i = 0; i < 8; i++)
#pragma unroll
        for (int j = 0; j < 4; j++) acc[i][j] = 0.f;

    unsigned xs_base = (unsigned)__cvta_generic_to_shared(
        &Xs[(m0 + (lane & 15)) * XS_STRIDE]) + (lane >> 4) * 16;
    unsigned ws_base = (unsigned)__cvta_generic_to_shared(
        &Ws[(lane & 15) * WS_STRIDE + n0]) + (lane >> 4) * 16;

#pragma unroll
    for (int k = 0; k < D; k += 16) {
        unsigned a[4];
        ldsm_x4(a[0], a[1], a[2], a[3], xs_base + k * 2);
        unsigned wrow = ws_base + k * (WS_STRIDE * 2);
#pragma unroll
        for (int q = 0; q < 4; q++) {       // 4 x (16-wide) = 64 cols
            unsigned b0, b1, b2, b3;
            ldsm_x4_t(b0, b1, b2, b3, wrow + q * 32);
            mma16816(acc[q * 2],     a, b0, b1);
            mma16816(acc[q * 2 + 1], a, b2, b3);
        }
    }

    int r0 = row0 + m0 + (lane >> 2);
    int cb = n0 + (lane & 3) * 2;
#pragma unroll
    for (int nt = 0; nt < 8; nt++) {
        int c = cb + nt * 8;
        if (r0 < nRows) {
            __half2 h = __floats2half2_rn(acc[nt][0], acc[nt][1]);
            *(__half2*)(Y + (size_t)r0 * D + c) = h;
        }
        if (r0 + 8 < nRows) {
            __half2 h = __floats2half2_rn(acc[nt][2], acc[nt][3]);
            *(__half2*)(Y + (size_t)(r0 + 8) * D + c) = h;
        }
    }
}

// ---------------------------------------------------------------------------
// CSR SpMM gather-reduce: one warp per dst node, fp16 rows, fp32 accumulate.
// MODE 0: out = raw sum, fp16          (layer 1; GEMM2 applies transform)
// MODE 1: out = relu(sum*nd + bias), fp32   (final h -> d_out)
// ---------------------------------------------------------------------------
template<int MODE>
__global__ __launch_bounds__(256) void csr_spmm(
    const __half* __restrict__ t, const int* __restrict__ rowptr,
    const int* __restrict__ esrc, const float* __restrict__ nd,
    const float* __restrict__ bias, void* __restrict__ outp, int nNodes)
{
    int node = blockIdx.x * 8 + (threadIdx.x >> 5);
    if (node >= nNodes) return;
    int lane = threadIdx.x & 31;
    int beg = rowptr[node];
    int end = rowptr[node + 1];

    float4 a0 = make_float4(0.f, 0.f, 0.f, 0.f);
    float4 a1 = make_float4(0.f, 0.f, 0.f, 0.f);
    float4 a2 = make_float4(0.f, 0.f, 0.f, 0.f);
    float4 a3 = make_float4(0.f, 0.f, 0.f, 0.f);

#define ACCUM(ACC, U)                                                     \
    {                                                                     \
        float2 f0 = __half22float2(*(const __half2*)&(U).x);              \
        float2 f1 = __half22float2(*(const __half2*)&(U).y);              \
        (ACC).x += f0.x; (ACC).y += f0.y; (ACC).z += f1.x; (ACC).w += f1.y;\
    }

    int j = beg;
    for (; j + 3 < end; j += 4) {
        int s0 = esrc[j], s1 = esrc[j + 1], s2 = esrc[j + 2], s3 = esrc[j + 3];
        uint2 v0 = __ldg((const uint2*)(t + (size_t)s0 * D) + lane);
        uint2 v1 = __ldg((const uint2*)(t + (size_t)s1 * D) + lane);
        uint2 v2 = __ldg((const uint2*)(t + (size_t)s2 * D) + lane);
        uint2 v3 = __ldg((const uint2*)(t + (size_t)s3 * D) + lane);
        ACCUM(a0, v0); ACCUM(a1, v1); ACCUM(a2, v2); ACCUM(a3, v3);
    }
    for (; j < end; j++) {
        int s = esrc[j];
        uint2 v = __ldg((const uint2*)(t + (size_t)s * D) + lane);
        ACCUM(a0, v);
    }
#undef ACCUM

    float4 acc;
    acc.x = (a0.x + a1.x) + (a2.x + a3.x);
    acc.y = (a0.y + a1.y) + (a2.y + a3.y);
    acc.z = (a0.z + a1.z) + (a2.z + a3.z);
    acc.w = (a0.w + a1.w) + (a2.w + a3.w);

    if (MODE == 1) {
        float a = nd[node];
        float4 bb = __ldg((const float4*)bias + lane);
        acc.x = fmaxf(fmaf(acc.x, a, bb.x), 0.f);
        acc.y = fmaxf(fmaf(acc.y, a, bb.y), 0.f);
        acc.z = fmaxf(fmaf(acc.z, a, bb.z), 0.f);
        acc.w = fmaxf(fmaf(acc.w, a, bb.w), 0.f);
        *(float4*)((float*)outp + (size_t)node * D + lane * 4) = acc;
    } else {
        __half2 h0 = __floats2half2_rn(acc.x, acc.y);
        __half2 h1 = __floats2half2_rn(acc.z, acc.w);
        uint2 p;
        p.x = *(unsigned*)&h0; p.y = *(unsigned*)&h1;
        *((uint2*)((__half*)outp + (size_t)node * D) + lane) = p;
    }
}

// ---------------------------------------------------------------------------
__device__ __forceinline__ int lower_bound_i(const int* a, int n, int v) {
    int lo = 0, hi = n;
    while (lo < hi) {
        int mid = (lo + hi) >> 1;
        if (a[mid] < v) lo = mid + 1; else hi = mid;
    }
    return lo;
}

// parallel pooling: grid (64, POOL_SLICES); partial sums -> atomicAdd into hg
__global__ void pool_partial(const float* __restrict__ h,
                             const int* __restrict__ gid,
                             int nNodes, float* __restrict__ hg) {
    int g = blockIdx.x;
    int slice = blockIdx.y;
    int t = threadIdx.x;   // 128 threads, one feature column each
    int lo = lower_bound_i(gid, nNodes, g);
    int hi = lower_bound_i(gid, nNodes, g + 1);
    int len = hi - lo;
    int s0r = lo + (int)((long long)len * slice / POOL_SLICES);
    int s1r = lo + (int)((long long)len * (slice + 1) / POOL_SLICES);

    float s0 = 0.f, s1 = 0.f, s2 = 0.f, s3 = 0.f;
    int r = s0r;
    for (; r + 3 < s1r; r += 4) {
        s0 += h[(size_t)r * D + t];
        s1 += h[(size_t)(r + 1) * D + t];
        s2 += h[(size_t)(r + 2) * D + t];
        s3 += h[(size_t)(r + 3) * D + t];
    }
    for (; r < s1r; r++) s0 += h[(size_t)r * D + t];
    float part = (s0 + s1) + (s2 + s3);
    atomicAdd(&hg[g * D + t], part);
}

// fused readout: normalize pooled sums then 2-layer MLP
__global__ void readout_fused(const float* __restrict__ hg,
                              const int* __restrict__ gid, int nNodes,
                              const float* __restrict__ Wr1,
                              const float* __restrict__ br1,
                              const float* __restrict__ Wr2,
                              const float* __restrict__ br2,
                              float* __restrict__ out) {
    __shared__ float row[D];
    __shared__ float mid[D];
    int g = blockIdx.x, t = threadIdx.x;
    int lo = lower_bound_i(gid, nNodes, g);
    int hi = lower_bound_i(gid, nNodes, g + 1);
    float inv = 1.0f / fmaxf((float)(hi - lo), 1.0f);
    row[t] = hg[g * D + t] * inv;
    __syncthreads();
    float acc = br1[t];
#pragma unroll 8
    for (int k = 0; k < D; k++) acc = fmaf(row[k], Wr1[k * D + t], acc);
    mid[t] = fmaxf(acc, 0.f);
    __syncthreads();
    float acc2 = br2[t];
#pragma unroll 8
    for (int k = 0; k < D; k++) acc2 = fmaf(mid[k], Wr2[k * D + t], acc2);
    out[g * D + t] = acc2;
}

// ---------------------------------------------------------------------------
extern "C" void kernel_launch(void* const* d_in, const int* in_sizes, int n_in,
                              void* d_out, int out_size) {
    const float* x   = (const float*)d_in[0];
    const int*   ei  = (const int*)d_in[1];
    const int*   gid = (const int*)d_in[2];
    int wbase = (n_in >= 12) ? 4 : 3;
    const float* W1  = (const float*)d_in[wbase + 0];
    const float* b1  = (const float*)d_in[wbase + 1];
    const float* W2  = (const float*)d_in[wbase + 2];
    const float* b2  = (const float*)d_in[wbase + 3];
    const float* Wr1 = (const float*)d_in[wbase + 4];
    const float* br1 = (const float*)d_in[wbase + 5];
    const float* Wr2 = (const float*)d_in[wbase + 6];
    const float* br2 = (const float*)d_in[wbase + 7];

    const int nNodes = in_sizes[0] / D;
    const int nE     = in_sizes[1] / 2;
    const int* src = ei;
    const int* dst = ei + nE;

    float* out_g = (float*)d_out;
    float* out_h = out_g + 64 * D;

    unsigned char* zr;
    int    *rowptr, *cursor, *esrc, *bsums;
    float  *nrm;
    __half *t, *agg1, *wh;
    cudaGetSymbolAddress((void**)&zr,     g_zeroed);
    cudaGetSymbolAddress((void**)&rowptr, g_rowptr);
    cudaGetSymbolAddress((void**)&cursor, g_cursor);
    cudaGetSymbolAddress((void**)&esrc,   g_esrc);
    cudaGetSymbolAddress((void**)&bsums,  g_bsums);
    cudaGetSymbolAddress((void**)&nrm,    g_norm);
    cudaGetSymbolAddress((void**)&t,      g_t);
    cudaGetSymbolAddress((void**)&agg1,   g_agg1);
    cudaGetSymbolAddress((void**)&wh,     g_wh);

    int*   hdst = (int*)zr;
    int*   hsrc = hdst + MAX_NODES;
    float* hg   = (float*)(zr + 2 * MAX_NODES * 4);
    float* ns = nrm;
    float* nd = nrm + MAX_NODES;
    __half* wh1 = wh;
    __half* wh2 = wh + D * D;

    const int smemGemm = (D * WS_STRIDE + 64 * XS_STRIDE) * (int)sizeof(__half);
    cudaFuncSetAttribute((gemm_mma<float, 0>),
                         cudaFuncAttributeMaxDynamicSharedMemorySize, smemGemm);
    cudaFuncSetAttribute((gemm_mma<__half, 1>),
                         cudaFuncAttributeMaxDynamicSharedMemorySize, smemGemm);

    const int nb = (nNodes + 1023) / 1024;
    int gemmBlocks = (nNodes + 63) / 64;
    int spmmBlocks = (nNodes + 7) / 8;
    int nE2 = (nE + 1) / 2;
    int histBlocks = (nE2 + 255) / 256;

    // single memset covers hist + hg
    cudaMemsetAsync(zr, 0, ZERO_BYTES, 0);

    // fused setup: W conversion + histograms, then norm+scan, expand, scatter
    convert_hist<<<32 + histBlocks, 256>>>(W1, W2, wh, src, dst, hdst, hsrc,
                                           nE);
    scan_bsums_norm<<<nb, 256>>>(hdst, hsrc, bsums, ns, nd, nNodes);
    scan_expand<<<nb, 256>>>(hdst, bsums, rowptr, cursor, nNodes, nE, nb);
    scatter_edges<<<histBlocks, 256>>>(src, dst, cursor, esrc, nE);

    // layer 1: t = (ns.x)@W1 ; agg1 = A t (raw, fp16)
    gemm_mma<float, 0><<<gemmBlocks, 256, smemGemm>>>(x, wh1, nullptr, ns,
                                                      nullptr, t, nNodes);
    csr_spmm<0><<<spmmBlocks, 256>>>(t, rowptr, esrc, nullptr, nullptr, agg1,
                                     nNodes);

    // layer 2: t = (relu(agg1.nd+b1).ns)@W2 ; h2 = relu((A t).nd+b2) -> d_out
    gemm_mma<__half, 1><<<gemmBlocks, 256, smemGemm>>>(agg1, wh2, b1, ns, nd, t,
                                                       nNodes);
    csr_spmm<1><<<spmmBlocks, 256>>>(t, rowptr, esrc, nd, b2, out_h, nNodes);

    // parallel pooling + fused readout MLP
    dim3 poolGrid(64, POOL_SLICES);
    pool_partial<<<poolGrid, D>>>(out_h, gid, nNodes, hg);
    readout_fused<<<64, D>>>(hg, gid, nNodes, Wr1, br1, Wr2, br2, out_g);
}

// round 13
// speedup vs baseline: 1.3452x; 1.3452x over previous
#include <cuda_runtime.h>
#include <cuda_fp16.h>

// ---------------------------------------------------------------------------
// GCN (CSR gather-reduce, fp16 intermediates, HMMA GEMM):
//   t1 = (ns . x) @ W1                                   (fp16 out)
//   agg1 = A t1                                          (fp16, raw)
//   t2 = (relu(agg1 . nd + b1) . ns) @ W2                (transform in GEMM2)
//   h2 = relu((A t2) . nd + b2)                          (fp32 -> d_out)
//   hg = sum-pool(h2) (parallel partials); readout divides by count
// ---------------------------------------------------------------------------

#define D 128
#define MAX_NODES 100096
#define MAX_EDGES 1700000
#define MAX_FEAT  12812288   // MAX_NODES * 128

#define WS_STRIDE 136
#define XS_STRIDE 136
#define POOL_SLICES 16

// scratch (device globals: allocation-free rule)
__device__ int    g_hist[2 * MAX_NODES];
__device__ int    g_rowptr[MAX_NODES + 1];
__device__ int    g_cursor[MAX_NODES];
__device__ int    g_esrc[MAX_EDGES];
__device__ int    g_bsums[256];
__device__ float  g_norm[2 * MAX_NODES];       // norm_src, norm_dst
__device__ __half g_wh[2 * D * D];             // fp16 W1, W2
__device__ __half g_t[MAX_FEAT];               // GEMM output (fp16)
__device__ __half g_agg1[MAX_FEAT];            // layer-1 raw aggregate (fp16)
__device__ float  g_hg[64 * D];                // pooled sums (atomic accum)

// ---------------------------------------------------------------------------
__global__ void convert_w(const float* __restrict__ W1,
                          const float* __restrict__ W2,
                          __half* __restrict__ wh) {
    int i = blockIdx.x * blockDim.x + threadIdx.x;   // 0..8191 (float2 units)
    const float2* w1 = (const float2*)W1;
    const float2* w2 = (const float2*)W2;
    float2 a = w1[i];
    float2 b = w2[i];
    ((__half2*)wh)[i] = __floats2half2_rn(a.x, a.y);
    ((__half2*)wh)[i + D * D / 2] = __floats2half2_rn(b.x, b.y);
}

// ---------------------------------------------------------------------------
__global__ void hist_kernel(const int* __restrict__ src,
                            const int* __restrict__ dst,
                            int* __restrict__ hdst, int* __restrict__ hsrc,
                            int nE) {
    int e2 = blockIdx.x * blockDim.x + threadIdx.x;
    int e = e2 * 2;
    if (e + 1 < nE) {
        int2 s = *(const int2*)(src + e);
        int2 d = *(const int2*)(dst + e);
        atomicAdd(&hsrc[s.x], 1); atomicAdd(&hsrc[s.y], 1);
        atomicAdd(&hdst[d.x], 1); atomicAdd(&hdst[d.y], 1);
    } else if (e < nE) {
        atomicAdd(&hsrc[src[e]], 1);
        atomicAdd(&hdst[dst[e]], 1);
    }
}

__global__ void norm_kernel(const int* __restrict__ hsrc,
                            const int* __restrict__ hdst,
                            float* __restrict__ ns, float* __restrict__ nd,
                            int n) {
    int i = blockIdx.x * blockDim.x + threadIdx.x;
    if (i < n) {
        ns[i] = rsqrtf(fmaxf((float)hsrc[i], 1.0f));
        nd[i] = rsqrtf(fmaxf((float)hdst[i], 1.0f));
    }
}

// ---------------- 2-kernel exclusive prefix scan over hist_dst -------------
__global__ void scan_bsums(const int* __restrict__ hist,
                           int* __restrict__ bsums, int n) {
    __shared__ int sh[256];
    int b = blockIdx.x, t = threadIdx.x;
    int base = b * 1024 + t * 4;
    int s = 0;
#pragma unroll
    for (int k = 0; k < 4; k++) { int i = base + k; if (i < n) s += hist[i]; }
    sh[t] = s; __syncthreads();
    for (int off = 128; off > 0; off >>= 1) {
        if (t < off) sh[t] += sh[t + off];
        __syncthreads();
    }
    if (t == 0) bsums[b] = sh[0];
}

// expand with inline block-offset scan
__global__ void scan_expand(const int* __restrict__ hist,
                            const int* __restrict__ bsums,
                            int* __restrict__ rowptr, int* __restrict__ cursor,
                            int n, int nE, int nb) {
    __shared__ int sbs[256];
    __shared__ int sh[256];
    int b = blockIdx.x, t = threadIdx.x;

    int v0 = (t < nb) ? bsums[t] : 0;
    sbs[t] = v0; __syncthreads();
    for (int off = 1; off < 256; off <<= 1) {
        int u = (t >= off) ? sbs[t - off] : 0;
        __syncthreads();
        sbs[t] += u;
        __syncthreads();
    }
    int boff = (b == 0) ? 0 : sbs[b - 1];

    int base = b * 1024 + t * 4;
    int v[4]; int s = 0;
#pragma unroll
    for (int k = 0; k < 4; k++) {
        int i = base + k;
        v[k] = (i < n) ? hist[i] : 0;
        s += v[k];
    }
    sh[t] = s; __syncthreads();
    for (int off = 1; off < 256; off <<= 1) {
        int u = (t >= off) ? sh[t - off] : 0;
        __syncthreads();
        sh[t] += u;
        __syncthreads();
    }
    int off = boff + sh[t] - s;
#pragma unroll
    for (int k = 0; k < 4; k++) {
        int i = base + k;
        if (i < n) { rowptr[i] = off; cursor[i] = off; }
        off += v[k];
    }
    if (b == 0 && t == 0) rowptr[n] = nE;
}

__global__ void scatter_edges(const int* __restrict__ src,
                              const int* __restrict__ dst,
                              int* __restrict__ cursor,
                              int* __restrict__ esrc, int nE) {
    int e2 = blockIdx.x * blockDim.x + threadIdx.x;
    int e = e2 * 2;
    if (e + 1 < nE) {
        int2 s = *(const int2*)(src + e);
        int2 d = *(const int2*)(dst + e);
        int p0 = atomicAdd(&cursor[d.x], 1);
        esrc[p0] = s.x;
        int p1 = atomicAdd(&cursor[d.y], 1);
        esrc[p1] = s.y;
    } else if (e < nE) {
        int p = atomicAdd(&cursor[dst[e]], 1);
        esrc[p] = src[e];
    }
}

// ---------------------------------------------------------------------------
// HMMA helpers
// ---------------------------------------------------------------------------
__device__ __forceinline__ void ldsm_x4(unsigned& r0, unsigned& r1,
                                        unsigned& r2, unsigned& r3,
                                        unsigned addr) {
    asm volatile("ldmatrix.sync.aligned.m8n8.x4.shared.b16 {%0,%1,%2,%3}, [%4];"
                 : "=r"(r0), "=r"(r1), "=r"(r2), "=r"(r3) : "r"(addr));
}
__device__ __forceinline__ void ldsm_x4_t(unsigned& r0, unsigned& r1,
                                          unsigned& r2, unsigned& r3,
                                          unsigned addr) {
    asm volatile("ldmatrix.sync.aligned.m8n8.x4.trans.shared.b16 {%0,%1,%2,%3}, [%4];"
                 : "=r"(r0), "=r"(r1), "=r"(r2), "=r"(r3) : "r"(addr));
}
__device__ __forceinline__ void mma16816(float* d, const unsigned* a,
                                         unsigned b0, unsigned b1) {
    asm volatile(
        "mma.sync.aligned.m16n8k16.row.col.f32.f16.f16.f32 "
        "{%0,%1,%2,%3}, {%4,%5,%6,%7}, {%8,%9}, {%0,%1,%2,%3};"
        : "+f"(d[0]), "+f"(d[1]), "+f"(d[2]), "+f"(d[3])
        : "r"(a[0]), "r"(a[1]), "r"(a[2]), "r"(a[3]), "r"(b0), "r"(b1));
}

// ---------------------------------------------------------------------------
// Fused HMMA GEMM: Y[r] = f(X[r]) @ W, K = N = 128, fp16 in / fp32 acc.
// W pre-converted fp16. 64-row tile, 8 warps (4 row x 2 col), acc[8][4].
// MODE 0 (TIN=float): f(x)[k] = x[k] * nsrc[r]
// MODE 1 (TIN=half):  f(x)[k] = relu(x[k]*ndst[r] + bias[k]) * nsrc[r]
// ---------------------------------------------------------------------------
template<typename TIN, int MODE>
__global__ __launch_bounds__(256, 1) void gemm_mma(
    const TIN* __restrict__ X, const __half* __restrict__ Wh,
    const float* __restrict__ bias, const float* __restrict__ nsrc,
    const float* __restrict__ ndst, __half* __restrict__ Y, int nRows)
{
    extern __shared__ __half sm[];
    __half* Ws = sm;                        // 128 x WS_STRIDE
    __half* Xs = sm + D * WS_STRIDE;        // 64 x XS_STRIDE
    const int tid = threadIdx.x;
    const int row0 = blockIdx.x * 64;

    // W (fp16 global) -> smem: pure uint4 copy (2048 uint4)
    {
        const uint4* Wg = (const uint4*)Wh;
#pragma unroll
        for (int i = 0; i < 8; i++) {
            int idx = tid + i * 256;        // uint4 idx over 2048
            int r = idx >> 4;               // 16 uint4 (128 halfs) per row
            int c = (idx & 15) * 8;
            *(uint4*)&Ws[r * WS_STRIDE + c] = Wg[idx];
        }
    }
    // X tile: 64 rows x 32 chunks(4), transform in fp32, pack fp16
    {
#pragma unroll
        for (int i = 0; i < 8; i++) {
            int linear = tid + i * 256;     // 2048 = 64 rows * 32 chunks
            int row = linear >> 5;
            int c4  = linear & 31;
            int gr  = row0 + row;
            float4 v = make_float4(0.f, 0.f, 0.f, 0.f);
            if (gr < nRows) {
                if constexpr (sizeof(TIN) == 4) {
                    v = ((const float4*)(X + (size_t)gr * D))[c4];
                } else {
                    uint2 u = ((const uint2*)(X + (size_t)gr * D))[c4];
                    float2 f0 = __half22float2(*(const __half2*)&u.x);
                    float2 f1 = __half22float2(*(const __half2*)&u.y);
                    v = make_float4(f0.x, f0.y, f1.x, f1.y);
                }
                if (MODE == 0) {
                    float s = nsrc[gr];
                    v.x *= s; v.y *= s; v.z *= s; v.w *= s;
                } else {
                    float a = ndst[gr];
                    float s = nsrc[gr];
                    float4 bb = ((const float4*)bias)[c4];
                    v.x = fmaxf(fmaf(v.x, a, bb.x), 0.f) * s;
                    v.y = fmaxf(fmaf(v.y, a, bb.y), 0.f) * s;
                    v.z = fmaxf(fmaf(v.z, a, bb.z), 0.f) * s;
                    v.w = fmaxf(fmaf(v.w, a, bb.w), 0.f) * s;
                }
            }
            __half2 h0 = __floats2half2_rn(v.x, v.y);
            __half2 h1 = __floats2half2_rn(v.z, v.w);
            uint2 p;
            p.x = *(unsigned*)&h0; p.y = *(unsigned*)&h1;
            *(uint2*)&Xs[row * XS_STRIDE + c4 * 4] = p;
        }
    }
    __syncthreads();

    const int warp = tid >> 5;
    const int lane = tid & 31;
    const int m0 = (warp & 3) * 16;
    const int n0 = (warp >> 2) * 64;

    float acc[8][4];
#pragma unroll
    for (int i = 0; i < 8; i++)
#pragma unroll
        for (int j = 0; j < 4; j++) acc[i][j] = 0.f;

    unsigned xs_base = (unsigned)__cvta_generic_to_shared(
        &Xs[(m0 + (lane & 15)) * XS_STRIDE]) + (lane >> 4) * 16;
    unsigned ws_base = (unsigned)__cvta_generic_to_shared(
        &Ws[(lane & 15) * WS_STRIDE + n0]) + (lane >> 4) * 16;

#pragma unroll
    for (int k = 0; k < D; k += 16) {
        unsigned a[4];
        ldsm_x4(a[0], a[1], a[2], a[3], xs_base + k * 2);
        unsigned wrow = ws_base + k * (WS_STRIDE * 2);
#pragma unroll
        for (int q = 0; q < 4; q++) {       // 4 x (16-wide) = 64 cols
            unsigned b0, b1, b2, b3;
            ldsm_x4_t(b0, b1, b2, b3, wrow + q * 32);
            mma16816(acc[q * 2],     a, b0, b1);
            mma16816(acc[q * 2 + 1], a, b2, b3);
        }
    }

    int r0 = row0 + m0 + (lane >> 2);
    int cb = n0 + (lane & 3) * 2;
#pragma unroll
    for (int nt = 0; nt < 8; nt++) {
        int c = cb + nt * 8;
        if (r0 < nRows) {
            __half2 h = __floats2half2_rn(acc[nt][0], acc[nt][1]);
            *(__half2*)(Y + (size_t)r0 * D + c) = h;
        }
        if (r0 + 8 < nRows) {
            __half2 h = __floats2half2_rn(acc[nt][2], acc[nt][3]);
            *(__half2*)(Y + (size_t)(r0 + 8) * D + c) = h;
        }
    }
}

// ---------------------------------------------------------------------------
// CSR SpMM gather-reduce: one warp per dst node, fp16 rows, fp32 accumulate.
// MODE 0: out = raw sum, fp16          (layer 1; GEMM2 applies transform)
// MODE 1: out = relu(sum*nd + bias), fp32   (final h -> d_out)
// ---------------------------------------------------------------------------
template<int MODE>
__global__ __launch_bounds__(256) void csr_spmm(
    const __half* __restrict__ t, const int* __restrict__ rowptr,
    const int* __restrict__ esrc, const float* __restrict__ nd,
    const float* __restrict__ bias, void* __restrict__ outp, int nNodes)
{
    int node = blockIdx.x * 8 + (threadIdx.x >> 5);
    if (node >= nNodes) return;
    int lane = threadIdx.x & 31;
    int beg = rowptr[node];
    int end = rowptr[node + 1];

    float4 a0 = make_float4(0.f, 0.f, 0.f, 0.f);
    float4 a1 = make_float4(0.f, 0.f, 0.f, 0.f);
    float4 a2 = make_float4(0.f, 0.f, 0.f, 0.f);
    float4 a3 = make_float4(0.f, 0.f, 0.f, 0.f);

#define ACCUM(ACC, U)                                                     \
    {                                                                     \
        float2 f0 = __half22float2(*(const __half2*)&(U).x);              \
        float2 f1 = __half22float2(*(const __half2*)&(U).y);              \
        (ACC).x += f0.x; (ACC).y += f0.y; (ACC).z += f1.x; (ACC).w += f1.y;\
    }

    int j = beg;
    for (; j + 3 < end; j += 4) {
        int s0 = esrc[j], s1 = esrc[j + 1], s2 = esrc[j + 2], s3 = esrc[j + 3];
        uint2 v0 = __ldg((const uint2*)(t + (size_t)s0 * D) + lane);
        uint2 v1 = __ldg((const uint2*)(t + (size_t)s1 * D) + lane);
        uint2 v2 = __ldg((const uint2*)(t + (size_t)s2 * D) + lane);
        uint2 v3 = __ldg((const uint2*)(t + (size_t)s3 * D) + lane);
        ACCUM(a0, v0); ACCUM(a1, v1); ACCUM(a2, v2); ACCUM(a3, v3);
    }
    for (; j < end; j++) {
        int s = esrc[j];
        uint2 v = __ldg((const uint2*)(t + (size_t)s * D) + lane);
        ACCUM(a0, v);
    }
#undef ACCUM

    float4 acc;
    acc.x = (a0.x + a1.x) + (a2.x + a3.x);
    acc.y = (a0.y + a1.y) + (a2.y + a3.y);
    acc.z = (a0.z + a1.z) + (a2.z + a3.z);
    acc.w = (a0.w + a1.w) + (a2.w + a3.w);

    if (MODE == 1) {
        float a = nd[node];
        float4 bb = __ldg((const float4*)bias + lane);
        acc.x = fmaxf(fmaf(acc.x, a, bb.x), 0.f);
        acc.y = fmaxf(fmaf(acc.y, a, bb.y), 0.f);
        acc.z = fmaxf(fmaf(acc.z, a, bb.z), 0.f);
        acc.w = fmaxf(fmaf(acc.w, a, bb.w), 0.f);
        *(float4*)((float*)outp + (size_t)node * D + lane * 4) = acc;
    } else {
        __half2 h0 = __floats2half2_rn(acc.x, acc.y);
        __half2 h1 = __floats2half2_rn(acc.z, acc.w);
        uint2 p;
        p.x = *(unsigned*)&h0; p.y = *(unsigned*)&h1;
        *((uint2*)((__half*)outp + (size_t)node * D) + lane) = p;
    }
}

// ---------------------------------------------------------------------------
__device__ __forceinline__ int lower_bound_i(const int* a, int n, int v) {
    int lo = 0, hi = n;
    while (lo < hi) {
        int mid = (lo + hi) >> 1;
        if (a[mid] < v) lo = mid + 1; else hi = mid;
    }
    return lo;
}

// parallel pooling: grid (64, POOL_SLICES); partial sums -> atomicAdd into hg
__global__ void pool_partial(const float* __restrict__ h,
                             const int* __restrict__ gid,
                             int nNodes, float* __restrict__ hg) {
    int g = blockIdx.x;
    int slice = blockIdx.y;
    int t = threadIdx.x;   // 128 threads, one feature column each
    int lo = lower_bound_i(gid, nNodes, g);
    int hi = lower_bound_i(gid, nNodes, g + 1);
    int len = hi - lo;
    int s0r = lo + (int)((long long)len * slice / POOL_SLICES);
    int s1r = lo + (int)((long long)len * (slice + 1) / POOL_SLICES);

    float s0 = 0.f, s1 = 0.f, s2 = 0.f, s3 = 0.f;
    int r = s0r;
    for (; r + 3 < s1r; r += 4) {
        s0 += h[(size_t)r * D + t];
        s1 += h[(size_t)(r + 1) * D + t];
        s2 += h[(size_t)(r + 2) * D + t];
        s3 += h[(size_t)(r + 3) * D + t];
    }
    for (; r < s1r; r++) s0 += h[(size_t)r * D + t];
    float part = (s0 + s1) + (s2 + s3);
    atomicAdd(&hg[g * D + t], part);
}

// fused readout: normalize pooled sums then 2-layer MLP
__global__ void readout_fused(const float* __restrict__ hg,
                              const int* __restrict__ gid, int nNodes,
                              const float* __restrict__ Wr1,
                              const float* __restrict__ br1,
                              const float* __restrict__ Wr2,
                              const float* __restrict__ br2,
                              float* __restrict__ out) {
    __shared__ float row[D];
    __shared__ float mid[D];
    int g = blockIdx.x, t = threadIdx.x;
    int lo = lower_bound_i(gid, nNodes, g);
    int hi = lower_bound_i(gid, nNodes, g + 1);
    float inv = 1.0f / fmaxf((float)(hi - lo), 1.0f);
    row[t] = hg[g * D + t] * inv;
    __syncthreads();
    float acc = br1[t];
#pragma unroll 8
    for (int k = 0; k < D; k++) acc = fmaf(row[k], Wr1[k * D + t], acc);
    mid[t] = fmaxf(acc, 0.f);
    __syncthreads();
    float acc2 = br2[t];
#pragma unroll 8
    for (int k = 0; k < D; k++) acc2 = fmaf(mid[k], Wr2[k * D + t], acc2);
    out[g * D + t] = acc2;
}

// ---------------------------------------------------------------------------
extern "C" void kernel_launch(void* const* d_in, const int* in_sizes, int n_in,
                              void* d_out, int out_size) {
    const float* x   = (const float*)d_in[0];
    const int*   ei  = (const int*)d_in[1];
    const int*   gid = (const int*)d_in[2];
    int wbase = (n_in >= 12) ? 4 : 3;
    const float* W1  = (const float*)d_in[wbase + 0];
    const float* b1  = (const float*)d_in[wbase + 1];
    const float* W2  = (const float*)d_in[wbase + 2];
    const float* b2  = (const float*)d_in[wbase + 3];
    const float* Wr1 = (const float*)d_in[wbase + 4];
    const float* br1 = (const float*)d_in[wbase + 5];
    const float* Wr2 = (const float*)d_in[wbase + 6];
    const float* br2 = (const float*)d_in[wbase + 7];

    const int nNodes = in_sizes[0] / D;
    const int nE     = in_sizes[1] / 2;
    const int* src = ei;
    const int* dst = ei + nE;

    float* out_g = (float*)d_out;
    float* out_h = out_g + 64 * D;

    int    *hist, *rowptr, *cursor, *esrc, *bsums;
    float  *nrm, *hg;
    __half *t, *agg1, *wh;
    cudaGetSymbolAddress((void**)&hist,   g_hist);
    cudaGetSymbolAddress((void**)&rowptr, g_rowptr);
    cudaGetSymbolAddress((void**)&cursor, g_cursor);
    cudaGetSymbolAddress((void**)&esrc,   g_esrc);
    cudaGetSymbolAddress((void**)&bsums,  g_bsums);
    cudaGetSymbolAddress((void**)&nrm,    g_norm);
    cudaGetSymbolAddress((void**)&t,      g_t);
    cudaGetSymbolAddress((void**)&agg1,   g_agg1);
    cudaGetSymbolAddress((void**)&wh,     g_wh);
    cudaGetSymbolAddress((void**)&hg,     g_hg);

    int* hdst = hist;
    int* hsrc = hist + MAX_NODES;
    float* ns = nrm;
    float* nd = nrm + MAX_NODES;
    __half* wh1 = wh;
    __half* wh2 = wh + D * D;

    const int smemGemm = (D * WS_STRIDE + 64 * XS_STRIDE) * (int)sizeof(__half);
    cudaFuncSetAttribute((gemm_mma<float, 0>),
                         cudaFuncAttributeMaxDynamicSharedMemorySize, smemGemm);
    cudaFuncSetAttribute((gemm_mma<__half, 1>),
                         cudaFuncAttributeMaxDynamicSharedMemorySize, smemGemm);

    const int nb = (nNodes + 1023) / 1024;
    int gemmBlocks = (nNodes + 63) / 64;
    int spmmBlocks = (nNodes + 7) / 8;
    int nE2 = (nE + 1) / 2;

    // zero hist + hg accumulators
    cudaMemsetAsync(hist, 0, 2 * (size_t)MAX_NODES * sizeof(int), 0);
    cudaMemsetAsync(hg, 0, 64 * D * sizeof(float), 0);

    // weight conversion + CSR build + norms
    convert_w<<<32, 256>>>(W1, W2, wh);
    hist_kernel<<<(nE2 + 255) / 256, 256>>>(src, dst, hdst, hsrc, nE);
    norm_kernel<<<(nNodes + 255) / 256, 256>>>(hsrc, hdst, ns, nd, nNodes);
    scan_bsums<<<nb, 256>>>(hdst, bsums, nNodes);
    scan_expand<<<nb, 256>>>(hdst, bsums, rowptr, cursor, nNodes, nE, nb);
    scatter_edges<<<(nE2 + 255) / 256, 256>>>(src, dst, cursor, esrc, nE);

    // layer 1: t = (ns.x)@W1 ; agg1 = A t (raw, fp16)
    gemm_mma<float, 0><<<gemmBlocks, 256, smemGemm>>>(x, wh1, nullptr, ns,
                                                      nullptr, t, nNodes);
    csr_spmm<0><<<spmmBlocks, 256>>>(t, rowptr, esrc, nullptr, nullptr, agg1,
                                     nNodes);

    // layer 2: t = (relu(agg1.nd+b1).ns)@W2 ; h2 = relu((A t).nd+b2) -> d_out
    gemm_mma<__half, 1><<<gemmBlocks, 256, smemGemm>>>(agg1, wh2, b1, ns, nd, t,
                                                       nNodes);
    csr_spmm<1><<<spmmBlocks, 256>>>(t, rowptr, esrc, nd, b2, out_h, nNodes);

    // parallel pooling + fused readout MLP
    dim3 poolGrid(64, POOL_SLICES);
    pool_partial<<<poolGrid, D>>>(out_h, gid, nNodes, hg);
    readout_fused<<<64, D>>>(hg, gid, nNodes, Wr1, br1, Wr2, br2, out_g);
}